// round 2
// baseline (speedup 1.0000x reference)
#include <cuda_runtime.h>
#include <stdint.h>

#define N_NODES   100000
#define N_EDGES   25000
#define NNZ_MAX   2000000
#define HO        64    // heads*out = feature width
#define IN_CH     64

// ---------------- scratch (device globals; no allocation) ----------------
__device__ __align__(16) float g_Xe[N_EDGES * HO];   // per-edge feature sums (6.4 MB)
__device__ float g_cnt[N_EDGES];                     // per-edge incidence count
__device__ float g_att[N_NODES];                     // per-vertex sum of homo[e]

// ---------------- helpers ----------------
__device__ __forceinline__ void red_add_v4(float* p, float4 v) {
    asm volatile("red.global.add.v4.f32 [%0], {%1,%2,%3,%4};"
                 :: "l"(p), "f"(v.x), "f"(v.y), "f"(v.z), "f"(v.w)
                 : "memory");
}

// ---------------- kernel 1: Xp = X @ W  -> out (d_out) ----------------
// 256 threads/block, 64 rows per block, 16 output channels per thread.
__global__ void gemm_kernel(const float* __restrict__ X,
                            const float* __restrict__ W,
                            float* __restrict__ out, int n)
{
    __shared__ float sW[64 * 64];
    __shared__ float sX[64 * 65];   // stride 65 -> conflict-free column reads

    const int t  = threadIdx.x;
    const int r0 = blockIdx.x * 64;

    #pragma unroll
    for (int idx = t; idx < 64 * 64; idx += 256) sW[idx] = W[idx];

    #pragma unroll
    for (int idx = t; idx < 64 * 64; idx += 256) {
        int r = idx >> 6, k = idx & 63;
        int gr = r0 + r;
        sX[r * 65 + k] = (gr < n) ? X[gr * 64 + k] : 0.f;
    }
    __syncthreads();

    const int row = t >> 2;       // 0..63
    const int q   = t & 3;        // 16-channel slab

    float4 a0 = {0,0,0,0}, a1 = {0,0,0,0}, a2 = {0,0,0,0}, a3 = {0,0,0,0};

    #pragma unroll 16
    for (int k = 0; k < 64; k++) {
        float x = sX[row * 65 + k];
        const float4* w4 = (const float4*)&sW[k * 64 + q * 16];
        float4 wa = w4[0], wb = w4[1], wc = w4[2], wd = w4[3];
        a0.x += x * wa.x; a0.y += x * wa.y; a0.z += x * wa.z; a0.w += x * wa.w;
        a1.x += x * wb.x; a1.y += x * wb.y; a1.z += x * wb.z; a1.w += x * wb.w;
        a2.x += x * wc.x; a2.y += x * wc.y; a2.z += x * wc.z; a2.w += x * wc.w;
        a3.x += x * wd.x; a3.y += x * wd.y; a3.z += x * wd.z; a3.w += x * wd.w;
    }

    int gr = r0 + row;
    if (gr < n) {
        float4* o = (float4*)&out[gr * 64 + q * 16];
        o[0] = a0; o[1] = a1; o[2] = a2; o[3] = a3;
    }
}

// ---------------- kernel 2: zero scratch ----------------
__global__ void zero_kernel()
{
    const int tot = N_EDGES * HO + N_EDGES + N_NODES;
    for (int idx = blockIdx.x * blockDim.x + threadIdx.x; idx < tot;
         idx += gridDim.x * blockDim.x) {
        if (idx < N_EDGES * HO)            g_Xe[idx] = 0.f;
        else if (idx < N_EDGES * HO + N_EDGES) g_cnt[idx - N_EDGES * HO] = 0.f;
        else                               g_att[idx - N_EDGES * HO - N_EDGES] = 0.f;
    }
}

// ---------------- kernel 3: vertex -> edge scatter (sums + counts + att_sum) --
// 16 threads per incidence; each thread owns one float4 channel group.
__global__ void scatter_edge_kernel(const float* __restrict__ Xp,
                                    const float* __restrict__ homo,
                                    const int*   __restrict__ vertex,
                                    const int*   __restrict__ edges,
                                    int nnz)
{
    int tid = blockIdx.x * blockDim.x + threadIdx.x;
    int i = tid >> 4;
    if (i >= nnz) return;
    int c = tid & 15;

    int v = vertex[i];
    int e = edges[i];

    float4 x = *(const float4*)&Xp[v * 64 + c * 4];
    red_add_v4(&g_Xe[e * 64 + c * 4], x);

    if (c == 0) {
        atomicAdd(&g_cnt[e], 1.0f);
        atomicAdd(&g_att[v], homo[e]);
    }
}

// ---------------- kernel 4: edge -> vertex scatter (attention-weighted) ------
// weight = (homo[e] / att_sum[v]) * (1 / max(cnt[e],1)); accumulates into out
// (which holds Xp, giving out = Xp + Xv).
__global__ void scatter_node_kernel(float* __restrict__ out,
                                    const float* __restrict__ homo,
                                    const int*   __restrict__ vertex,
                                    const int*   __restrict__ edges,
                                    int nnz)
{
    int tid = blockIdx.x * blockDim.x + threadIdx.x;
    int i = tid >> 4;
    if (i >= nnz) return;
    int c = tid & 15;

    int v = vertex[i];
    int e = edges[i];

    float w = homo[e] / (g_att[v] * fmaxf(g_cnt[e], 1.0f));

    float4 xe = *(const float4*)&g_Xe[e * 64 + c * 4];
    float4 r;
    r.x = w * xe.x; r.y = w * xe.y; r.z = w * xe.z; r.w = w * xe.w;
    red_add_v4(&out[v * 64 + c * 4], r);
}

// ---------------- kernel 5: row L2 normalize (detached norm) ----------------
// one warp per row; each lane owns 2 floats.
__global__ void normalize_kernel(float* __restrict__ out, int n)
{
    int warp = (blockIdx.x * blockDim.x + threadIdx.x) >> 5;
    if (warp >= n) return;
    int lane = threadIdx.x & 31;

    float2 v = *(float2*)&out[warp * 64 + lane * 2];
    float s = v.x * v.x + v.y * v.y;
    #pragma unroll
    for (int o = 16; o; o >>= 1) s += __shfl_xor_sync(0xffffffffu, s, o);

    float norm  = sqrtf(s);
    float scale = (norm > 0.f) ? (1.f / fmaxf(norm, 1e-30f)) : 0.f;
    v.x *= scale; v.y *= scale;
    *(float2*)&out[warp * 64 + lane * 2] = v;
}

// ---------------- launch ----------------
extern "C" void kernel_launch(void* const* d_in, const int* in_sizes, int n_in,
                              void* d_out, int out_size)
{
    const float* X      = (const float*)d_in[0];
    const float* W      = (const float*)d_in[1];
    const float* homo   = (const float*)d_in[2];
    const int*   vertex = (const int*)  d_in[3];
    const int*   edges  = (const int*)  d_in[4];
    float*       out    = (float*)d_out;

    const int n   = in_sizes[0] / IN_CH;   // 100000
    const int nnz = in_sizes[3];           // 2000000

    // 1) projection (writes Xp into out)
    gemm_kernel<<<(n + 63) / 64, 256>>>(X, W, out, n);

    // 2) clear scratch
    {
        const int tot = N_EDGES * HO + N_EDGES + N_NODES;
        zero_kernel<<<(tot + 255) / 256, 256>>>();
    }

    // 3) node -> edge aggregation
    {
        long long threads = (long long)nnz * 16;
        int grid = (int)((threads + 255) / 256);
        scatter_edge_kernel<<<grid, 256>>>(out, homo, vertex, edges, nnz);
    }

    // 4) edge -> node aggregation (accumulates onto Xp in out)
    {
        long long threads = (long long)nnz * 16;
        int grid = (int)((threads + 255) / 256);
        scatter_node_kernel<<<grid, 256>>>(out, homo, vertex, edges, nnz);
    }

    // 5) row-L2 normalize in place
    {
        int warps_per_block = 256 / 32;
        int grid = (n + warps_per_block - 1) / warps_per_block;
        normalize_kernel<<<grid, 256>>>(out, n);
    }
}

// round 3
// speedup vs baseline: 1.0362x; 1.0362x over previous
#include <cuda_runtime.h>
#include <stdint.h>

#define N_NODES   100000
#define N_EDGES   25000
#define NNZ_MAX   2000000
#define HO        64
#define IN_CH     64

// ---------------- scratch (device globals; no allocation) ----------------
__device__ __align__(16) float g_Xe[N_EDGES * HO];    // per-edge mean features (6.4 MB)
__device__ int g_ecnt[N_EDGES];                        // histogram by edge
__device__ int g_vcnt[N_NODES];                        // histogram by vertex
__device__ int g_erow[N_EDGES + 1];                    // CSR rowptr by edge
__device__ int g_vrow[N_NODES + 1];                    // CSR rowptr by vertex
__device__ int g_eoff[N_EDGES];                        // working offsets (permute)
__device__ int g_voff[N_NODES];
__device__ int g_evid[NNZ_MAX];                        // edge-CSR: vertex ids (8 MB)
__device__ int g_veid[NNZ_MAX];                        // vertex-CSR: edge ids (8 MB)

// ---------------- kernel 1: Xp = X @ W  -> out (d_out) ----------------
__global__ void gemm_kernel(const float* __restrict__ X,
                            const float* __restrict__ W,
                            float* __restrict__ out, int n)
{
    __shared__ float sW[64 * 64];
    __shared__ float sX[64 * 65];

    const int t  = threadIdx.x;
    const int r0 = blockIdx.x * 64;

    #pragma unroll
    for (int idx = t; idx < 64 * 64; idx += 256) sW[idx] = W[idx];
    #pragma unroll
    for (int idx = t; idx < 64 * 64; idx += 256) {
        int r = idx >> 6, k = idx & 63;
        int gr = r0 + r;
        sX[r * 65 + k] = (gr < n) ? X[gr * 64 + k] : 0.f;
    }
    __syncthreads();

    const int row = t >> 2;
    const int q   = t & 3;

    float4 a0 = {0,0,0,0}, a1 = {0,0,0,0}, a2 = {0,0,0,0}, a3 = {0,0,0,0};
    #pragma unroll 16
    for (int k = 0; k < 64; k++) {
        float x = sX[row * 65 + k];
        const float4* w4 = (const float4*)&sW[k * 64 + q * 16];
        float4 wa = w4[0], wb = w4[1], wc = w4[2], wd = w4[3];
        a0.x += x * wa.x; a0.y += x * wa.y; a0.z += x * wa.z; a0.w += x * wa.w;
        a1.x += x * wb.x; a1.y += x * wb.y; a1.z += x * wb.z; a1.w += x * wb.w;
        a2.x += x * wc.x; a2.y += x * wc.y; a2.z += x * wc.z; a2.w += x * wc.w;
        a3.x += x * wd.x; a3.y += x * wd.y; a3.z += x * wd.z; a3.w += x * wd.w;
    }
    int gr = r0 + row;
    if (gr < n) {
        float4* o = (float4*)&out[gr * 64 + q * 16];
        o[0] = a0; o[1] = a1; o[2] = a2; o[3] = a3;
    }
}

// ---------------- kernel 2: zero histogram counters ----------------
__global__ void zero_cnt_kernel()
{
    int idx = blockIdx.x * blockDim.x + threadIdx.x;
    if (idx < N_EDGES) g_ecnt[idx] = 0;
    if (idx < N_NODES) g_vcnt[idx] = 0;
}

// ---------------- kernel 3: histograms ----------------
__global__ void hist_kernel(const int* __restrict__ vertex,
                            const int* __restrict__ edges, int nnz)
{
    int i = blockIdx.x * blockDim.x + threadIdx.x;
    if (i >= nnz) return;
    atomicAdd(&g_ecnt[edges[i]], 1);
    atomicAdd(&g_vcnt[vertex[i]], 1);
}

// ---------------- kernel 4: exclusive scans (block 0: edges, block 1: nodes) --
// 1024 threads; shuffle-based warp scan + smem warp-sum scan, carried chunks.
__global__ void scan_kernel()
{
    const int  n   = (blockIdx.x == 0) ? N_EDGES : N_NODES;
    int* __restrict__ cnt = (blockIdx.x == 0) ? g_ecnt : g_vcnt;
    int* __restrict__ row = (blockIdx.x == 0) ? g_erow : g_vrow;
    int* __restrict__ off = (blockIdx.x == 0) ? g_eoff : g_voff;

    __shared__ int s_wsum[32];
    __shared__ int s_carry;

    const int lane = threadIdx.x & 31;
    const int wid  = threadIdx.x >> 5;
    if (threadIdx.x == 0) s_carry = 0;
    __syncthreads();

    for (int base = 0; base < n; base += 1024) {
        int i = base + threadIdx.x;
        int x = (i < n) ? cnt[i] : 0;

        // warp inclusive scan
        int v = x;
        #pragma unroll
        for (int o = 1; o < 32; o <<= 1) {
            int t = __shfl_up_sync(0xffffffffu, v, o);
            if (lane >= o) v += t;
        }
        if (lane == 31) s_wsum[wid] = v;
        __syncthreads();

        if (wid == 0) {
            int w = s_wsum[lane];
            int u = w;
            #pragma unroll
            for (int o = 1; o < 32; o <<= 1) {
                int t = __shfl_up_sync(0xffffffffu, u, o);
                if (lane >= o) u += t;
            }
            s_wsum[lane] = u - w;   // exclusive offsets per warp
        }
        __syncthreads();

        int excl = v - x + s_wsum[wid] + s_carry;
        if (i < n) { row[i] = excl; off[i] = excl; }

        __syncthreads();
        if (threadIdx.x == 1023) s_carry += v + s_wsum[31];
        __syncthreads();
    }
    if (threadIdx.x == 0) row[n] = s_carry;
}

// ---------------- kernel 5: permutation scatter (build CSR col arrays) -------
__global__ void permute_kernel(const int* __restrict__ vertex,
                               const int* __restrict__ edges, int nnz)
{
    int i = blockIdx.x * blockDim.x + threadIdx.x;
    if (i >= nnz) return;
    int v = vertex[i];
    int e = edges[i];
    int se = atomicAdd(&g_eoff[e], 1);
    g_evid[se] = v;
    int sv = atomicAdd(&g_voff[v], 1);
    g_veid[sv] = e;
}

// ---------------- kernel 6: edge aggregation (mean), one warp per edge -------
__global__ void edge_agg_kernel(const float* __restrict__ Xp)
{
    int e = (blockIdx.x * blockDim.x + threadIdx.x) >> 5;
    if (e >= N_EDGES) return;
    int lane = threadIdx.x & 31;

    int beg = g_erow[e], end = g_erow[e + 1];
    float2 acc = {0.f, 0.f};

    #pragma unroll 4
    for (int j = beg; j < end; j++) {
        int v = g_evid[j];                      // broadcast load
        float2 x = *(const float2*)&Xp[v * 64 + lane * 2];
        acc.x += x.x; acc.y += x.y;
    }
    int deg = end - beg;
    float inv = (deg > 0) ? (1.f / (float)deg) : 0.f;
    acc.x *= inv; acc.y *= inv;
    *(float2*)&g_Xe[e * 64 + lane * 2] = acc;
}

// ---------------- kernel 7: node aggregation + residual + L2 normalize -------
__global__ void node_agg_kernel(float* __restrict__ out,
                                const float* __restrict__ homo, int n)
{
    int v = (blockIdx.x * blockDim.x + threadIdx.x) >> 5;
    if (v >= n) return;
    int lane = threadIdx.x & 31;

    int beg = g_vrow[v], end = g_vrow[v + 1];

    // pass 1: att_sum for this vertex
    float wsum = 0.f;
    for (int j = beg + lane; j < end; j += 32) wsum += homo[g_veid[j]];
    #pragma unroll
    for (int o = 16; o; o >>= 1) wsum += __shfl_xor_sync(0xffffffffu, wsum, o);
    float invw = (wsum > 0.f) ? (1.f / wsum) : 0.f;

    // pass 2: acc = Xp[v] + sum_e att * Xe[e]
    float2 acc = *(const float2*)&out[v * 64 + lane * 2];
    #pragma unroll 4
    for (int j = beg; j < end; j++) {
        int e = g_veid[j];                      // broadcast load
        float w = homo[e] * invw;               // broadcast load
        float2 xe = *(const float2*)&g_Xe[e * 64 + lane * 2];
        acc.x += w * xe.x; acc.y += w * xe.y;
    }

    // fused row-L2 normalize (detached norm)
    float s = acc.x * acc.x + acc.y * acc.y;
    #pragma unroll
    for (int o = 16; o; o >>= 1) s += __shfl_xor_sync(0xffffffffu, s, o);
    float norm  = sqrtf(s);
    float scale = (norm > 0.f) ? (1.f / fmaxf(norm, 1e-30f)) : 0.f;
    acc.x *= scale; acc.y *= scale;
    *(float2*)&out[v * 64 + lane * 2] = acc;
}

// ---------------- launch ----------------
extern "C" void kernel_launch(void* const* d_in, const int* in_sizes, int n_in,
                              void* d_out, int out_size)
{
    const float* X      = (const float*)d_in[0];
    const float* W      = (const float*)d_in[1];
    const float* homo   = (const float*)d_in[2];
    const int*   vertex = (const int*)  d_in[3];
    const int*   edges  = (const int*)  d_in[4];
    float*       out    = (float*)d_out;

    const int n   = in_sizes[0] / IN_CH;   // 100000
    const int nnz = in_sizes[3];           // 2000000

    // 1) projection (Xp -> out)
    gemm_kernel<<<(n + 63) / 64, 256>>>(X, W, out, n);

    // 2) CSR build
    zero_cnt_kernel<<<(N_NODES + 255) / 256, 256>>>();
    hist_kernel<<<(nnz + 255) / 256, 256>>>(vertex, edges, nnz);
    scan_kernel<<<2, 1024>>>();
    permute_kernel<<<(nnz + 255) / 256, 256>>>(vertex, edges, nnz);

    // 3) node -> edge mean aggregation (register accumulation)
    edge_agg_kernel<<<(N_EDGES * 32 + 255) / 256, 256>>>(out);

    // 4) edge -> node attention aggregation + residual + normalize
    node_agg_kernel<<<((long long)n * 32 + 255) / 256, 256>>>(out, homo, n);
}

// round 4
// speedup vs baseline: 1.2833x; 1.2385x over previous
#include <cuda_runtime.h>
#include <stdint.h>

#define N_NODES   100000
#define N_EDGES   25000
#define NNZ_MAX   2000000
#define HO        64
#define IN_CH     64

#define TILE      4096                         // scan tile (1024 thr x 4)
#define TE        ((N_EDGES + TILE - 1) / TILE)   // 7
#define TV        ((N_NODES + TILE - 1) / TILE)   // 25

// ---------------- scratch (device globals; no allocation) ----------------
__device__ __align__(16) float g_Xe[N_EDGES * HO];
__device__ int g_ecnt[N_EDGES];
__device__ int g_vcnt[N_NODES];
__device__ int g_erow[N_EDGES + 1];
__device__ int g_vrow[N_NODES + 1];
__device__ int g_eoff[N_EDGES];
__device__ int g_voff[N_NODES];
__device__ int g_evid[NNZ_MAX];
__device__ int g_veid[NNZ_MAX];
__device__ int g_epart[TE];
__device__ int g_vpart[TV];

// ---------------- kernel 1: Xp = X @ W  -> out ----------------
__global__ void gemm_kernel(const float* __restrict__ X,
                            const float* __restrict__ W,
                            float* __restrict__ out, int n)
{
    __shared__ float sW[64 * 64];
    __shared__ float sX[64 * 65];

    const int t  = threadIdx.x;
    const int r0 = blockIdx.x * 64;

    #pragma unroll
    for (int idx = t; idx < 64 * 64; idx += 256) sW[idx] = W[idx];
    #pragma unroll
    for (int idx = t; idx < 64 * 64; idx += 256) {
        int r = idx >> 6, k = idx & 63;
        int gr = r0 + r;
        sX[r * 65 + k] = (gr < n) ? X[gr * 64 + k] : 0.f;
    }
    __syncthreads();

    const int row = t >> 2;
    const int q   = t & 3;

    float4 a0 = {0,0,0,0}, a1 = {0,0,0,0}, a2 = {0,0,0,0}, a3 = {0,0,0,0};
    #pragma unroll 16
    for (int k = 0; k < 64; k++) {
        float x = sX[row * 65 + k];
        const float4* w4 = (const float4*)&sW[k * 64 + q * 16];
        float4 wa = w4[0], wb = w4[1], wc = w4[2], wd = w4[3];
        a0.x += x * wa.x; a0.y += x * wa.y; a0.z += x * wa.z; a0.w += x * wa.w;
        a1.x += x * wb.x; a1.y += x * wb.y; a1.z += x * wb.z; a1.w += x * wb.w;
        a2.x += x * wc.x; a2.y += x * wc.y; a2.z += x * wc.z; a2.w += x * wc.w;
        a3.x += x * wd.x; a3.y += x * wd.y; a3.z += x * wd.z; a3.w += x * wd.w;
    }
    int gr = r0 + row;
    if (gr < n) {
        float4* o = (float4*)&out[gr * 64 + q * 16];
        o[0] = a0; o[1] = a1; o[2] = a2; o[3] = a3;
    }
}

// ---------------- kernel 2: zero histogram counters ----------------
__global__ void zero_cnt_kernel()
{
    int idx = blockIdx.x * blockDim.x + threadIdx.x;
    if (idx < N_EDGES) g_ecnt[idx] = 0;
    if (idx < N_NODES) g_vcnt[idx] = 0;
}

// ---------------- kernel 3: histograms ----------------
__global__ void hist_kernel(const int* __restrict__ vertex,
                            const int* __restrict__ edges, int nnz)
{
    int i = blockIdx.x * blockDim.x + threadIdx.x;
    if (i >= nnz) return;
    atomicAdd(&g_ecnt[edges[i]], 1);
    atomicAdd(&g_vcnt[vertex[i]], 1);
}

// ---------------- scan phase 1: per-tile partial sums ----------------
// blocks [0, TE): edge tiles; blocks [TE, TE+TV): vertex tiles. 1024 threads.
__global__ void scan_partial_kernel()
{
    const bool is_e = blockIdx.x < TE;
    const int  tile = is_e ? blockIdx.x : blockIdx.x - TE;
    const int  n    = is_e ? N_EDGES : N_NODES;
    const int* __restrict__ cnt = is_e ? g_ecnt : g_vcnt;
    int* __restrict__ part      = is_e ? g_epart : g_vpart;

    __shared__ int s_wsum[32];
    const int lane = threadIdx.x & 31;
    const int wid  = threadIdx.x >> 5;

    int base = tile * TILE + threadIdx.x * 4;
    int s = 0;
    #pragma unroll
    for (int k = 0; k < 4; k++) {
        int i = base + k;
        if (i < n) s += cnt[i];
    }
    #pragma unroll
    for (int o = 16; o; o >>= 1) s += __shfl_xor_sync(0xffffffffu, s, o);
    if (lane == 0) s_wsum[wid] = s;
    __syncthreads();
    if (wid == 0) {
        int w = s_wsum[lane];
        #pragma unroll
        for (int o = 16; o; o >>= 1) w += __shfl_xor_sync(0xffffffffu, w, o);
        if (lane == 0) part[tile] = w;
    }
}

// ---------------- scan phase 2: scan the partials (one tiny block) ----------
__global__ void scan_spine_kernel()
{
    // lane-parallel exclusive scan of TE and TV partials (each <= 32)
    const int lane = threadIdx.x & 31;
    const int wid  = threadIdx.x >> 5;
    if (wid == 0) {
        int x = (lane < TE) ? g_epart[lane] : 0;
        int v = x;
        #pragma unroll
        for (int o = 1; o < 32; o <<= 1) {
            int t = __shfl_up_sync(0xffffffffu, v, o);
            if (lane >= o) v += t;
        }
        if (lane < TE) g_epart[lane] = v - x;
        if (lane == 31) g_erow[N_EDGES] = v;
    } else if (wid == 1) {
        int x = (lane < TV) ? g_vpart[lane] : 0;
        int v = x;
        #pragma unroll
        for (int o = 1; o < 32; o <<= 1) {
            int t = __shfl_up_sync(0xffffffffu, v, o);
            if (lane >= o) v += t;
        }
        if (lane < TV) g_vpart[lane] = v - x;
        if (lane == 31) g_vrow[N_NODES] = v;
    }
}

// ---------------- scan phase 3: local scan + tile offset ----------------
__global__ void scan_final_kernel()
{
    const bool is_e = blockIdx.x < TE;
    const int  tile = is_e ? blockIdx.x : blockIdx.x - TE;
    const int  n    = is_e ? N_EDGES : N_NODES;
    const int* __restrict__ cnt = is_e ? g_ecnt : g_vcnt;
    const int* __restrict__ part= is_e ? g_epart : g_vpart;
    int* __restrict__ row       = is_e ? g_erow : g_vrow;
    int* __restrict__ off       = is_e ? g_eoff : g_voff;

    __shared__ int s_wsum[32];
    const int lane = threadIdx.x & 31;
    const int wid  = threadIdx.x >> 5;

    int base = tile * TILE + threadIdx.x * 4;
    int c[4];
    int s = 0;
    #pragma unroll
    for (int k = 0; k < 4; k++) {
        int i = base + k;
        c[k] = (i < n) ? cnt[i] : 0;
        s += c[k];
    }

    // warp inclusive scan of thread sums
    int v = s;
    #pragma unroll
    for (int o = 1; o < 32; o <<= 1) {
        int t = __shfl_up_sync(0xffffffffu, v, o);
        if (lane >= o) v += t;
    }
    if (lane == 31) s_wsum[wid] = v;
    __syncthreads();
    if (wid == 0) {
        int w = s_wsum[lane];
        int u = w;
        #pragma unroll
        for (int o = 1; o < 32; o <<= 1) {
            int t = __shfl_up_sync(0xffffffffu, u, o);
            if (lane >= o) u += t;
        }
        s_wsum[lane] = u - w;
    }
    __syncthreads();

    int excl = part[tile] + s_wsum[wid] + (v - s);   // exclusive prefix of this thread
    #pragma unroll
    for (int k = 0; k < 4; k++) {
        int i = base + k;
        if (i < n) { row[i] = excl; off[i] = excl; }
        excl += c[k];
    }
}

// ---------------- kernel 5: permutation scatter (build CSR col arrays) -------
__global__ void permute_kernel(const int* __restrict__ vertex,
                               const int* __restrict__ edges, int nnz)
{
    int i = blockIdx.x * blockDim.x + threadIdx.x;
    if (i >= nnz) return;
    int v = vertex[i];
    int e = edges[i];
    int se = atomicAdd(&g_eoff[e], 1);
    g_evid[se] = v;
    int sv = atomicAdd(&g_voff[v], 1);
    g_veid[sv] = e;
}

// ---------------- kernel 6: edge aggregation (mean), one warp per edge -------
__global__ void edge_agg_kernel(const float* __restrict__ Xp)
{
    int e = (blockIdx.x * blockDim.x + threadIdx.x) >> 5;
    if (e >= N_EDGES) return;
    int lane = threadIdx.x & 31;

    int beg = g_erow[e], end = g_erow[e + 1];
    float2 acc = {0.f, 0.f};

    #pragma unroll 4
    for (int j = beg; j < end; j++) {
        int v = g_evid[j];
        float2 x = *(const float2*)&Xp[v * 64 + lane * 2];
        acc.x += x.x; acc.y += x.y;
    }
    int deg = end - beg;
    float inv = (deg > 0) ? (1.f / (float)deg) : 0.f;
    acc.x *= inv; acc.y *= inv;
    *(float2*)&g_Xe[e * 64 + lane * 2] = acc;
}

// ---------------- kernel 7: node aggregation + residual + L2 normalize -------
__global__ void node_agg_kernel(float* __restrict__ out,
                                const float* __restrict__ homo, int n)
{
    int v = (blockIdx.x * blockDim.x + threadIdx.x) >> 5;
    if (v >= n) return;
    int lane = threadIdx.x & 31;

    int beg = g_vrow[v], end = g_vrow[v + 1];

    float wsum = 0.f;
    for (int j = beg + lane; j < end; j += 32) wsum += homo[g_veid[j]];
    #pragma unroll
    for (int o = 16; o; o >>= 1) wsum += __shfl_xor_sync(0xffffffffu, wsum, o);
    float invw = (wsum > 0.f) ? (1.f / wsum) : 0.f;

    float2 acc = *(const float2*)&out[v * 64 + lane * 2];
    #pragma unroll 4
    for (int j = beg; j < end; j++) {
        int e = g_veid[j];
        float w = homo[e] * invw;
        float2 xe = *(const float2*)&g_Xe[e * 64 + lane * 2];
        acc.x += w * xe.x; acc.y += w * xe.y;
    }

    float s = acc.x * acc.x + acc.y * acc.y;
    #pragma unroll
    for (int o = 16; o; o >>= 1) s += __shfl_xor_sync(0xffffffffu, s, o);
    float norm  = sqrtf(s);
    float scale = (norm > 0.f) ? (1.f / fmaxf(norm, 1e-30f)) : 0.f;
    acc.x *= scale; acc.y *= scale;
    *(float2*)&out[v * 64 + lane * 2] = acc;
}

// ---------------- launch ----------------
extern "C" void kernel_launch(void* const* d_in, const int* in_sizes, int n_in,
                              void* d_out, int out_size)
{
    const float* X      = (const float*)d_in[0];
    const float* W      = (const float*)d_in[1];
    const float* homo   = (const float*)d_in[2];
    const int*   vertex = (const int*)  d_in[3];
    const int*   edges  = (const int*)  d_in[4];
    float*       out    = (float*)d_out;

    const int n   = in_sizes[0] / IN_CH;   // 100000
    const int nnz = in_sizes[3];           // 2000000

    gemm_kernel<<<(n + 63) / 64, 256>>>(X, W, out, n);

    zero_cnt_kernel<<<(N_NODES + 255) / 256, 256>>>();
    hist_kernel<<<(nnz + 255) / 256, 256>>>(vertex, edges, nnz);

    scan_partial_kernel<<<TE + TV, 1024>>>();
    scan_spine_kernel<<<1, 64>>>();
    scan_final_kernel<<<TE + TV, 1024>>>();

    permute_kernel<<<(nnz + 255) / 256, 256>>>(vertex, edges, nnz);

    edge_agg_kernel<<<(N_EDGES * 32 + 255) / 256, 256>>>(out);
    node_agg_kernel<<<((long long)n * 32 + 255) / 256, 256>>>(out, homo, n);
}

// round 5
// speedup vs baseline: 1.3740x; 1.0706x over previous
#include <cuda_runtime.h>
#include <stdint.h>

#define N_NODES   100000
#define N_EDGES   25000
#define NNZ_MAX   2000000
#define HO        64
#define IN_CH     64

#define TILE      4096
#define TE        ((N_EDGES + TILE - 1) / TILE)   // 7
#define TV        ((N_NODES + TILE - 1) / TILE)   // 25

// ---------------- scratch (device globals; no allocation) ----------------
__device__ __align__(16) float g_Xe[N_EDGES * HO];
__device__ int   g_ecnt[N_EDGES];
__device__ int   g_vcnt[N_NODES];
__device__ float g_att[N_NODES];
__device__ int   g_erow[N_EDGES + 1];
__device__ int   g_vrow[N_NODES + 1];
__device__ int   g_eoff[N_EDGES];
__device__ int   g_voff[N_NODES];
__device__ int   g_evid[NNZ_MAX];
__device__ int   g_veid[NNZ_MAX];
__device__ int   g_epart[TE];
__device__ int   g_vpart[TV];

// ---------------- kernel A: zero counters ----------------
__global__ void zero_kernel()
{
    int idx = blockIdx.x * blockDim.x + threadIdx.x;
    if (idx < N_EDGES) g_ecnt[idx] = 0;
    if (idx < N_NODES) { g_vcnt[idx] = 0; g_att[idx] = 0.f; }
}

// ---------------- kernel B: fused GEMM (Xp = X@W -> out) + histograms -------
// blocks [0, gemm_blocks): gemm; blocks >= gemm_blocks: histogram + att_sum.
__global__ void gemm_hist_kernel(const float* __restrict__ X,
                                 const float* __restrict__ W,
                                 float* __restrict__ out,
                                 const float* __restrict__ homo,
                                 const int* __restrict__ vertex,
                                 const int* __restrict__ edges,
                                 int n, int nnz, int gemm_blocks)
{
    __shared__ float sW[64 * 64];
    __shared__ float sX[64 * 65];

    if (blockIdx.x < gemm_blocks) {
        const int t  = threadIdx.x;
        const int r0 = blockIdx.x * 64;

        #pragma unroll
        for (int idx = t; idx < 64 * 64; idx += 256) sW[idx] = W[idx];
        #pragma unroll
        for (int idx = t; idx < 64 * 64; idx += 256) {
            int r = idx >> 6, k = idx & 63;
            int gr = r0 + r;
            sX[r * 65 + k] = (gr < n) ? X[gr * 64 + k] : 0.f;
        }
        __syncthreads();

        const int row = t >> 2;
        const int q   = t & 3;

        float4 a0 = {0,0,0,0}, a1 = {0,0,0,0}, a2 = {0,0,0,0}, a3 = {0,0,0,0};
        #pragma unroll 16
        for (int k = 0; k < 64; k++) {
            float x = sX[row * 65 + k];
            const float4* w4 = (const float4*)&sW[k * 64 + q * 16];
            float4 wa = w4[0], wb = w4[1], wc = w4[2], wd = w4[3];
            a0.x += x * wa.x; a0.y += x * wa.y; a0.z += x * wa.z; a0.w += x * wa.w;
            a1.x += x * wb.x; a1.y += x * wb.y; a1.z += x * wb.z; a1.w += x * wb.w;
            a2.x += x * wc.x; a2.y += x * wc.y; a2.z += x * wc.z; a2.w += x * wc.w;
            a3.x += x * wd.x; a3.y += x * wd.y; a3.z += x * wd.z; a3.w += x * wd.w;
        }
        int gr = r0 + row;
        if (gr < n) {
            float4* o = (float4*)&out[gr * 64 + q * 16];
            o[0] = a0; o[1] = a1; o[2] = a2; o[3] = a3;
        }
        return;
    }

    // ---- histogram part: 4 incidences per thread ----
    int b = blockIdx.x - gemm_blocks;
    int i = (b * 256 + threadIdx.x) * 4;
    if (i + 3 < nnz) {
        int4 v = *(const int4*)&vertex[i];
        int4 e = *(const int4*)&edges[i];
        atomicAdd(&g_ecnt[e.x], 1); atomicAdd(&g_ecnt[e.y], 1);
        atomicAdd(&g_ecnt[e.z], 1); atomicAdd(&g_ecnt[e.w], 1);
        atomicAdd(&g_vcnt[v.x], 1); atomicAdd(&g_vcnt[v.y], 1);
        atomicAdd(&g_vcnt[v.z], 1); atomicAdd(&g_vcnt[v.w], 1);
        atomicAdd(&g_att[v.x], homo[e.x]); atomicAdd(&g_att[v.y], homo[e.y]);
        atomicAdd(&g_att[v.z], homo[e.z]); atomicAdd(&g_att[v.w], homo[e.w]);
    } else {
        for (int k = i; k < nnz; k++) {
            int v = vertex[k], e = edges[k];
            atomicAdd(&g_ecnt[e], 1);
            atomicAdd(&g_vcnt[v], 1);
            atomicAdd(&g_att[v], homo[e]);
        }
    }
}

// ---------------- scan phase 1: per-tile partial sums ----------------
__global__ void scan_partial_kernel()
{
    const bool is_e = blockIdx.x < TE;
    const int  tile = is_e ? blockIdx.x : blockIdx.x - TE;
    const int  n    = is_e ? N_EDGES : N_NODES;
    const int* __restrict__ cnt = is_e ? g_ecnt : g_vcnt;
    int* __restrict__ part      = is_e ? g_epart : g_vpart;

    __shared__ int s_wsum[32];
    const int lane = threadIdx.x & 31;
    const int wid  = threadIdx.x >> 5;

    int base = tile * TILE + threadIdx.x * 4;
    int s = 0;
    #pragma unroll
    for (int k = 0; k < 4; k++) {
        int i = base + k;
        if (i < n) s += cnt[i];
    }
    #pragma unroll
    for (int o = 16; o; o >>= 1) s += __shfl_xor_sync(0xffffffffu, s, o);
    if (lane == 0) s_wsum[wid] = s;
    __syncthreads();
    if (wid == 0) {
        int w = s_wsum[lane];
        #pragma unroll
        for (int o = 16; o; o >>= 1) w += __shfl_xor_sync(0xffffffffu, w, o);
        if (lane == 0) part[tile] = w;
    }
}

// ---------------- scan phase 2: local scan + inline spine ----------------
__global__ void scan_final_kernel()
{
    const bool is_e = blockIdx.x < TE;
    const int  tile = is_e ? blockIdx.x : blockIdx.x - TE;
    const int  n    = is_e ? N_EDGES : N_NODES;
    const int  nt   = is_e ? TE : TV;
    const int* __restrict__ cnt = is_e ? g_ecnt : g_vcnt;
    const int* __restrict__ part= is_e ? g_epart : g_vpart;
    int* __restrict__ row       = is_e ? g_erow : g_vrow;
    int* __restrict__ off       = is_e ? g_eoff : g_voff;

    __shared__ int s_wsum[32];
    __shared__ int s_tile_off;
    const int lane = threadIdx.x & 31;
    const int wid  = threadIdx.x >> 5;

    // inline spine: warp 0 scans all tile partials
    if (wid == 0) {
        int p = (lane < nt) ? part[lane] : 0;
        int incl = p;
        #pragma unroll
        for (int o = 1; o < 32; o <<= 1) {
            int t = __shfl_up_sync(0xffffffffu, incl, o);
            if (lane >= o) incl += t;
        }
        if (lane == tile) s_tile_off = incl - p;
        if (tile == 0 && lane == nt - 1) row[n] = incl;
    }

    int base = tile * TILE + threadIdx.x * 4;
    int c[4];
    int s = 0;
    #pragma unroll
    for (int k = 0; k < 4; k++) {
        int i = base + k;
        c[k] = (i < n) ? cnt[i] : 0;
        s += c[k];
    }

    int v = s;
    #pragma unroll
    for (int o = 1; o < 32; o <<= 1) {
        int t = __shfl_up_sync(0xffffffffu, v, o);
        if (lane >= o) v += t;
    }
    if (lane == 31) s_wsum[wid] = v;
    __syncthreads();
    if (wid == 0) {
        int w = s_wsum[lane];
        int u = w;
        #pragma unroll
        for (int o = 1; o < 32; o <<= 1) {
            int t = __shfl_up_sync(0xffffffffu, u, o);
            if (lane >= o) u += t;
        }
        s_wsum[lane] = u - w;
    }
    __syncthreads();

    int excl = s_tile_off + s_wsum[wid] + (v - s);
    #pragma unroll
    for (int k = 0; k < 4; k++) {
        int i = base + k;
        if (i < n) { row[i] = excl; off[i] = excl; }
        excl += c[k];
    }
}

// ---------------- kernel: permutation scatter ----------------
__global__ void permute_kernel(const int* __restrict__ vertex,
                               const int* __restrict__ edges, int nnz)
{
    int i = blockIdx.x * blockDim.x + threadIdx.x;
    if (i >= nnz) return;
    int v = vertex[i];
    int e = edges[i];
    int se = atomicAdd(&g_eoff[e], 1);
    g_evid[se] = v;
    int sv = atomicAdd(&g_voff[v], 1);
    g_veid[sv] = e;
}

// ---------------- kernel: edge aggregation (mean), warp/edge, 2-way ILP -----
__global__ void edge_agg_kernel(const float* __restrict__ Xp)
{
    int e = (blockIdx.x * blockDim.x + threadIdx.x) >> 5;
    if (e >= N_EDGES) return;
    const int lane = threadIdx.x & 31;
    const int h = lane >> 4;        // half-warp id: processes j = beg+h, +2, ...
    const int c = lane & 15;        // float4 channel slot (16 x 4 = 64 ch)

    int beg = g_erow[e], end = g_erow[e + 1];
    float4 acc = {0.f, 0.f, 0.f, 0.f};

    #pragma unroll 2
    for (int j = beg + h; j < end; j += 2) {
        int v = g_evid[j];
        float4 x = *(const float4*)&Xp[v * 64 + c * 4];
        acc.x += x.x; acc.y += x.y; acc.z += x.z; acc.w += x.w;
    }
    // combine halves
    acc.x += __shfl_xor_sync(0xffffffffu, acc.x, 16);
    acc.y += __shfl_xor_sync(0xffffffffu, acc.y, 16);
    acc.z += __shfl_xor_sync(0xffffffffu, acc.z, 16);
    acc.w += __shfl_xor_sync(0xffffffffu, acc.w, 16);

    int deg = end - beg;
    float inv = (deg > 0) ? (1.f / (float)deg) : 0.f;
    if (h == 0) {
        float4 r = { acc.x * inv, acc.y * inv, acc.z * inv, acc.w * inv };
        *(float4*)&g_Xe[e * 64 + c * 4] = r;
    }
}

// ---------------- kernel: node aggregation + residual + L2 norm, 2-way ILP --
__global__ void node_agg_kernel(float* __restrict__ out,
                                const float* __restrict__ homo, int n)
{
    int v = (blockIdx.x * blockDim.x + threadIdx.x) >> 5;
    if (v >= n) return;
    const int lane = threadIdx.x & 31;
    const int h = lane >> 4;
    const int c = lane & 15;

    int beg = g_vrow[v], end = g_vrow[v + 1];

    float wsum = g_att[v];
    float invw = (wsum > 0.f) ? (1.f / wsum) : 0.f;

    float4 acc = {0.f, 0.f, 0.f, 0.f};
    #pragma unroll 2
    for (int j = beg + h; j < end; j += 2) {
        int e = g_veid[j];
        float w = homo[e] * invw;
        float4 xe = *(const float4*)&g_Xe[e * 64 + c * 4];
        acc.x += w * xe.x; acc.y += w * xe.y;
        acc.z += w * xe.z; acc.w += w * xe.w;
    }
    acc.x += __shfl_xor_sync(0xffffffffu, acc.x, 16);
    acc.y += __shfl_xor_sync(0xffffffffu, acc.y, 16);
    acc.z += __shfl_xor_sync(0xffffffffu, acc.z, 16);
    acc.w += __shfl_xor_sync(0xffffffffu, acc.w, 16);

    // residual (Xp lives in out)
    float4 r = *(const float4*)&out[v * 64 + c * 4];
    acc.x += r.x; acc.y += r.y; acc.z += r.z; acc.w += r.w;

    // row-L2 norm: both halves hold identical values; butterfly within half
    float s = acc.x * acc.x + acc.y * acc.y + acc.z * acc.z + acc.w * acc.w;
    #pragma unroll
    for (int o = 8; o; o >>= 1) s += __shfl_xor_sync(0xffffffffu, s, o);

    float norm  = sqrtf(s);
    float scale = (norm > 0.f) ? (1.f / fmaxf(norm, 1e-30f)) : 0.f;
    if (h == 0) {
        float4 w = { acc.x * scale, acc.y * scale, acc.z * scale, acc.w * scale };
        *(float4*)&out[v * 64 + c * 4] = w;
    }
}

// ---------------- launch ----------------
extern "C" void kernel_launch(void* const* d_in, const int* in_sizes, int n_in,
                              void* d_out, int out_size)
{
    const float* X      = (const float*)d_in[0];
    const float* W      = (const float*)d_in[1];
    const float* homo   = (const float*)d_in[2];
    const int*   vertex = (const int*)  d_in[3];
    const int*   edges  = (const int*)  d_in[4];
    float*       out    = (float*)d_out;

    const int n   = in_sizes[0] / IN_CH;   // 100000
    const int nnz = in_sizes[3];           // 2000000

    zero_kernel<<<(N_NODES + 255) / 256, 256>>>();

    const int gemm_blocks = (n + 63) / 64;
    const int hist_blocks = (nnz + 1023) / 1024;
    gemm_hist_kernel<<<gemm_blocks + hist_blocks, 256>>>(
        X, W, out, homo, vertex, edges, n, nnz, gemm_blocks);

    scan_partial_kernel<<<TE + TV, 1024>>>();
    scan_final_kernel<<<TE + TV, 1024>>>();

    permute_kernel<<<(nnz + 255) / 256, 256>>>(vertex, edges, nnz);

    edge_agg_kernel<<<(N_EDGES * 32 + 255) / 256, 256>>>(out);
    node_agg_kernel<<<((long long)n * 32 + 255) / 256, 256>>>(out, homo, n);
}